// round 17
// baseline (speedup 1.0000x reference)
#include <cuda_runtime.h>
#include <cuda_fp16.h>
#include <math.h>
#include <stdint.h>

#define B_ 8
#define S_ 1024
#define D_ 1024
#define NH_ 16
#define NKV_ 8
#define HD_ 64
#define M_ (B_*S_)

// ---------------------------------------------------------------------------
// Scratch (allocation-free rule: __device__ globals)
// ---------------------------------------------------------------------------
__device__ __half g_xh[M_*D_],  g_xl[M_*D_];            // x hi/lo fp16
__device__ __half g_wqf[D_*D_];                         // weights^T single fp16
__device__ __half g_wkf[(D_/2)*D_];
__device__ __half g_wvf[(D_/2)*D_];
__device__ __half g_wof[D_*D_];
__device__ __half g_qf[M_*NH_*HD_];                     // roped q single fp16 (x0.125)
__device__ __half g_kf[M_*NKV_*HD_];                    // roped k single fp16
__device__ __half g_vf[M_*NKV_*HD_];                    // v single fp16
__device__ __half g_aof[M_*NH_*HD_];                    // attn out single fp16

// ---------------------------------------------------------------------------
// helpers
// ---------------------------------------------------------------------------
__device__ __forceinline__ uint32_t smem_u32(const void* p) {
    uint32_t a;
    asm("{ .reg .u64 t; cvta.to.shared.u64 t, %1; cvt.u32.u64 %0, t; }" : "=r"(a) : "l"(p));
    return a;
}
__device__ __forceinline__ void ldsm_x4(uint32_t addr, uint32_t* d) {
    asm volatile("ldmatrix.sync.aligned.m8n8.x4.shared.b16 {%0,%1,%2,%3}, [%4];"
                 : "=r"(d[0]), "=r"(d[1]), "=r"(d[2]), "=r"(d[3]) : "r"(addr));
}
__device__ __forceinline__ void ldsm_x4_t(uint32_t addr, uint32_t* d) {
    asm volatile("ldmatrix.sync.aligned.m8n8.x4.trans.shared.b16 {%0,%1,%2,%3}, [%4];"
                 : "=r"(d[0]), "=r"(d[1]), "=r"(d[2]), "=r"(d[3]) : "r"(addr));
}
__device__ __forceinline__ void mma_f16(float* c, const uint32_t* a, const uint32_t* b) {
    asm volatile(
        "mma.sync.aligned.m16n8k16.row.col.f32.f16.f16.f32 "
        "{%0,%1,%2,%3}, {%4,%5,%6,%7}, {%8,%9}, {%0,%1,%2,%3};"
        : "+f"(c[0]), "+f"(c[1]), "+f"(c[2]), "+f"(c[3])
        : "r"(a[0]), "r"(a[1]), "r"(a[2]), "r"(a[3]), "r"(b[0]), "r"(b[1]));
}
__device__ __forceinline__ void cp16(uint32_t dst, const void* src) {
    asm volatile("cp.async.cg.shared.global [%0], [%1], 16;" :: "r"(dst), "l"(src) : "memory");
}
__device__ __forceinline__ void cp_commit() {
    asm volatile("cp.async.commit_group;" ::: "memory");
}
template<int N> __device__ __forceinline__ void cp_wait() {
    asm volatile("cp.async.wait_group %0;" :: "n"(N) : "memory");
}
__device__ __forceinline__ uint32_t pk_h2(float lo, float hi) {
    __half2 t;
    t.x = __float2half_rn(lo);
    t.y = __float2half_rn(hi);
    return *reinterpret_cast<uint32_t*>(&t);
}
__device__ __forceinline__ float h_hi(float x, float* rem) {
    __half h = __float2half_rn(x);
    float hf = __half2float(h);
    *rem = x - hf;
    return hf;
}

// ---------------------------------------------------------------------------
// elementwise: fp32 -> hi/lo fp16 (for x)
// ---------------------------------------------------------------------------
__global__ void split_h(const float* __restrict__ src,
                        __half* __restrict__ dh,
                        __half* __restrict__ dl, int n4)
{
    int i = blockIdx.x * blockDim.x + threadIdx.x;
    if (i >= n4) return;
    float4 f = *(const float4*)(src + (size_t)i * 4);
    float r0, r1, r2, r3;
    float h0 = h_hi(f.x, &r0), h1 = h_hi(f.y, &r1);
    float h2 = h_hi(f.z, &r2), h3 = h_hi(f.w, &r3);
    *(uint2*)(dh + (size_t)i * 4) = make_uint2(pk_h2(h0, h1), pk_h2(h2, h3));
    *(uint2*)(dl + (size_t)i * 4) = make_uint2(pk_h2(r0, r1), pk_h2(r2, r3));
}

// ---------------------------------------------------------------------------
// transpose + single fp16 convert: W[K,N] fp32 -> T[N,K] fp16
// ---------------------------------------------------------------------------
__global__ void trans_conv(const float* __restrict__ W,
                           __half* __restrict__ Tf, int N, int K)
{
    __shared__ float t[32][33];
    const int n0 = blockIdx.x * 32, k0 = blockIdx.y * 32;
    const int tx = threadIdx.x, ty = threadIdx.y;
#pragma unroll
    for (int i = 0; i < 4; i++)
        t[ty + i * 8][tx] = W[(size_t)(k0 + ty + i * 8) * N + n0 + tx];
    __syncthreads();
#pragma unroll
    for (int i = 0; i < 4; i++) {
        size_t o = (size_t)(n0 + ty + i * 8) * K + k0 + tx;
        Tf[o] = __float2half_rn(t[tx][ty + i * 8]);
    }
}

// ---------------------------------------------------------------------------
// HMMA GEMM: (Ah [+ Al if npass==2]) x single-fp16 B^T, cp.async 2-stage.
// Epilogue modes: 0 fp32 C | 2 RoPE+scale+fp16 | 3 fp16
// ---------------------------------------------------------------------------
#define LDPAD 40
#define HG_TILEB (128 * LDPAD * 2)     // 10240
#define HG_STAGEB (3 * HG_TILEB)       // 30720
#define HG_SMEM (2 * HG_STAGEB)        // 61440

__global__ __launch_bounds__(256, 2) void hgemm2(const __half* __restrict__ Ah,
                                                 const __half* __restrict__ Al,
                                                 const __half* __restrict__ Bf,
                                                 float* __restrict__ C32,
                                                 __half* __restrict__ Ch,
                                                 const float* __restrict__ cs,
                                                 const float* __restrict__ sn,
                                                 int N, int K, int mode, float scale,
                                                 int npass)
{
    extern __shared__ __align__(16) char dsm[];
    const uint32_t uD = smem_u32(dsm);

    const int tid = threadIdx.x, lane = tid & 31, wid = tid >> 5;
    const int bn = blockIdx.x, bm = blockIdx.y;
    const int warp_m = (wid & 1) * 64;
    const int warp_n = (wid >> 1) * 32;

    const int row  = tid >> 1;
    const int half = tid & 1;
    const __half* pAh = Ah + (size_t)(bm * 128 + row) * K + half * 16;
    const __half* pAl = Al + (size_t)(bm * 128 + row) * K + half * 16;
    const __half* pBf = Bf + (size_t)(bn * 128 + row) * K + half * 16;
    const uint32_t fill_off = (uint32_t)(row * LDPAD + half * 16) * 2;

    const int g = lane >> 3, r = lane & 7;
    uint32_t aoff[4], boff[2];
#pragma unroll
    for (int mt = 0; mt < 4; mt++)
        aoff[mt] = ((warp_m + mt * 16 + (g & 1) * 8 + r) * LDPAD + (g >> 1) * 8) * 2;
#pragma unroll
    for (int nt2 = 0; nt2 < 2; nt2++)
        boff[nt2] = ((warp_n + nt2 * 16 + (g >> 1) * 8 + r) * LDPAD + (g & 1) * 8) * 2;

    float acc[4][4][4];
#pragma unroll
    for (int i = 0; i < 4; i++)
#pragma unroll
        for (int j = 0; j < 4; j++)
#pragma unroll
            for (int t = 0; t < 4; t++) acc[i][j][t] = 0.f;

    const int NCH = K / 32;

    // prologue: stage 0
    {
        const uint32_t d = uD + fill_off;
        cp16(d,                pAh); cp16(d + 16,                pAh + 8);
        if (npass == 2) { cp16(d + HG_TILEB, pAl); cp16(d + HG_TILEB + 16, pAl + 8); }
        cp16(d + 2 * HG_TILEB, pBf); cp16(d + 2 * HG_TILEB + 16, pBf + 8);
        cp_commit();
    }

    for (int ch = 0; ch < NCH; ch++) {
        if (ch + 1 < NCH) {
            const int k1 = (ch + 1) * 32;
            const uint32_t d = uD + ((ch + 1) & 1) * HG_STAGEB + fill_off;
            cp16(d,                pAh + k1); cp16(d + 16,                pAh + k1 + 8);
            if (npass == 2) {
                cp16(d + HG_TILEB, pAl + k1); cp16(d + HG_TILEB + 16, pAl + k1 + 8);
            }
            cp16(d + 2 * HG_TILEB, pBf + k1); cp16(d + 2 * HG_TILEB + 16, pBf + k1 + 8);
            cp_commit();
            cp_wait<1>();
        } else {
            cp_wait<0>();
        }
        __syncthreads();

        const uint32_t uSt = uD + (ch & 1) * HG_STAGEB;
        const uint32_t uAh = uSt, uAl = uSt + HG_TILEB, uBf = uSt + 2 * HG_TILEB;
#pragma unroll
        for (int ks = 0; ks < 2; ks++) {
            const uint32_t kadd = ks * 32;
            uint32_t bfr[2][4], afr[4][4];
#pragma unroll
            for (int nt2 = 0; nt2 < 2; nt2++) ldsm_x4(uBf + boff[nt2] + kadd, bfr[nt2]);
#pragma unroll
            for (int mt = 0; mt < 4; mt++) ldsm_x4(uAh + aoff[mt] + kadd, afr[mt]);
#pragma unroll
            for (int mt = 0; mt < 4; mt++)
#pragma unroll
                for (int nt = 0; nt < 4; nt++)
                    mma_f16(acc[mt][nt], afr[mt], bfr[nt >> 1] + (nt & 1) * 2);
            if (npass == 2) {
#pragma unroll
                for (int mt = 0; mt < 4; mt++) ldsm_x4(uAl + aoff[mt] + kadd, afr[mt]);
#pragma unroll
                for (int mt = 0; mt < 4; mt++)
#pragma unroll
                    for (int nt = 0; nt < 4; nt++)
                        mma_f16(acc[mt][nt], afr[mt], bfr[nt >> 1] + (nt & 1) * 2);
            }
        }
        __syncthreads();
    }

    // ---- epilogue ----
    const int erow = lane >> 2;
    const int ecol = (lane & 3) * 2;
#pragma unroll
    for (int mt = 0; mt < 4; mt++) {
#pragma unroll
        for (int nt = 0; nt < 4; nt++) {
            const int gr = bm * 128 + warp_m + mt * 16 + erow;
            const int gc = bn * 128 + warp_n + nt * 8 + ecol;
            float a0 = acc[mt][nt][0], a1 = acc[mt][nt][1];
            float a2 = acc[mt][nt][2], a3 = acc[mt][nt][3];
            if (mode == 0) {
                float* Cr = C32 + (size_t)gr * N + gc;
                *(float2*)Cr                   = make_float2(a0, a1);
                *(float2*)(Cr + 8 * (size_t)N) = make_float2(a2, a3);
            } else if (mode == 3) {
                *(uint32_t*)(Ch + (size_t)gr * N + gc)       = pk_h2(a0, a1);
                *(uint32_t*)(Ch + (size_t)(gr + 8) * N + gc) = pk_h2(a2, a3);
            } else {   // mode 2: RoPE + scale + single fp16
                const int d2 = (gc & 63) >> 1;
                const int s0 = gr & (S_ - 1), s1 = (gr + 8) & (S_ - 1);
                const float c0 = cs[s0 * 32 + d2], t0 = sn[s0 * 32 + d2];
                const float c1 = cs[s1 * 32 + d2], t1 = sn[s1 * 32 + d2];
                float r0 = (a0 * c0 - a1 * t0) * scale;
                float r1 = (a0 * t0 + a1 * c0) * scale;
                float r2 = (a2 * c1 - a3 * t1) * scale;
                float r3 = (a2 * t1 + a3 * c1) * scale;
                *(uint32_t*)(Ch + (size_t)gr * N + gc)       = pk_h2(r0, r1);
                *(uint32_t*)(Ch + (size_t)(gr + 8) * N + gc) = pk_h2(r2, r3);
            }
        }
    }
}

// ---------------------------------------------------------------------------
// HMMA flash attention, all single fp16 (Q, K, V, P). cp.async 2-stage K/V.
// ---------------------------------------------------------------------------
#define APAD 72
#define TILE_E (64 * APAD)
#define AT_TILEB (TILE_E * 2)          // 9216
#define AT_STAGEB (2 * AT_TILEB)       // 18432
#define AT_SMEM (2 * AT_STAGEB)        // 36864

__global__ __launch_bounds__(256) void attn_mma2(const __half* __restrict__ qf,
                                                 const __half* __restrict__ kf,
                                                 const __half* __restrict__ vf,
                                                 __half* __restrict__ aof)
{
    extern __shared__ __align__(16) char dsm[];
    __half* sm = (__half*)dsm;
    const uint32_t uD = smem_u32(dsm);

    const int tid = threadIdx.x, lane = tid & 31, wid = tid >> 5;
    const int qt = blockIdx.x, h = blockIdx.y, b = blockIdx.z;
    const int kvh = h >> 1;
    const int lg = lane >> 3, lr = lane & 7;
    const int quad = lane >> 2, qd = lane & 3;

    // ---- Q stage (single fp16; 128x72 tile fits in stage-0 region) ----
    {
        const int row = tid >> 1, half = tid & 1;
        const size_t gq = (((size_t)(b * S_ + qt * 128 + row)) * NH_ + h) * HD_ + half * 32;
        __half* dh = sm + row * APAD + half * 32;
#pragma unroll
        for (int i = 0; i < 4; i++) *(uint4*)(dh + i * 8) = *(const uint4*)(qf + gq + i * 8);
    }
    __syncthreads();

    uint32_t qfr[4][4];
    {
        const int rowa = wid * 16 + (lg & 1) * 8 + lr;
#pragma unroll
        for (int kc = 0; kc < 4; kc++) {
            const uint32_t off = (uint32_t)(rowa * APAD + (lg >> 1) * 8 + kc * 16) * 2;
            ldsm_x4(uD + off, qfr[kc]);
        }
    }
    __syncthreads();   // Q reads done before cp.async overwrites stage 0

    float o[8][4];
#pragma unroll
    for (int t = 0; t < 8; t++)
#pragma unroll
        for (int j = 0; j < 4; j++) o[t][j] = 0.f;
    float m0 = -1e30f, m1 = -1e30f, l0 = 0.f, l1 = 0.f;

    const int qbaseG = qt * 128 + wid * 16;
    const int lim0 = (qbaseG + quad) | 7;
    const int lim1 = (qbaseG + quad + 8) | 7;
    const int ntiles = 2 * qt + 2;

    const int krow = tid >> 2, kc4 = (tid & 3) * 16;
    const uint32_t fill_off = (uint32_t)(krow * APAD + kc4) * 2;

    {
        const size_t gkv = (((size_t)(b * S_ + krow)) * NKV_ + kvh) * HD_ + kc4;
        const uint32_t d = uD + fill_off;
        cp16(d,            kf + gkv); cp16(d + 16,            kf + gkv + 8);
        cp16(d + AT_TILEB, vf + gkv); cp16(d + AT_TILEB + 16, vf + gkv + 8);
        cp_commit();
    }

    for (int kt = 0; kt < ntiles; kt++) {
        if (kt + 1 < ntiles) {
            const size_t gkv = (((size_t)(b * S_ + (kt + 1) * 64 + krow)) * NKV_ + kvh) * HD_ + kc4;
            const uint32_t d = uD + ((kt + 1) & 1) * AT_STAGEB + fill_off;
            cp16(d,            kf + gkv); cp16(d + 16,            kf + gkv + 8);
            cp16(d + AT_TILEB, vf + gkv); cp16(d + AT_TILEB + 16, vf + gkv + 8);
            cp_commit();
            cp_wait<1>();
        } else {
            cp_wait<0>();
        }
        __syncthreads();

        if (kt * 64 <= qbaseG + 15) {
            const uint32_t uSt = uD + (kt & 1) * AT_STAGEB;
            const uint32_t uKf = uSt, uVf = uSt + AT_TILEB;

            // ---- S = Q @ K^T (single pass) ----
            float s[8][4];
#pragma unroll
            for (int t = 0; t < 8; t++)
#pragma unroll
                for (int j = 0; j < 4; j++) s[t][j] = 0.f;

#pragma unroll
            for (int kc = 0; kc < 4; kc++) {
#pragma unroll
                for (int nt2 = 0; nt2 < 4; nt2++) {
                    const uint32_t boff =
                        (uint32_t)((nt2 * 16 + (lg >> 1) * 8 + lr) * APAD + (lg & 1) * 8 + kc * 16) * 2;
                    uint32_t f[4];
                    ldsm_x4(uKf + boff, f);
                    mma_f16(s[nt2 * 2],     qfr[kc], f);
                    mma_f16(s[nt2 * 2 + 1], qfr[kc], f + 2);
                }
            }

            // ---- block-causal mask ----
            if (kt * 64 + 63 > qbaseG + 7) {
#pragma unroll
                for (int t = 0; t < 8; t++) {
                    const int key = kt * 64 + t * 8 + qd * 2;
                    if (key     > lim0) s[t][0] = -1e30f;
                    if (key + 1 > lim0) s[t][1] = -1e30f;
                    if (key     > lim1) s[t][2] = -1e30f;
                    if (key + 1 > lim1) s[t][3] = -1e30f;
                }
            }

            // ---- online softmax ----
            float mx0 = -1e30f, mx1 = -1e30f;
#pragma unroll
            for (int t = 0; t < 8; t++) {
                mx0 = fmaxf(mx0, fmaxf(s[t][0], s[t][1]));
                mx1 = fmaxf(mx1, fmaxf(s[t][2], s[t][3]));
            }
            mx0 = fmaxf(mx0, __shfl_xor_sync(0xffffffffu, mx0, 1));
            mx0 = fmaxf(mx0, __shfl_xor_sync(0xffffffffu, mx0, 2));
            mx1 = fmaxf(mx1, __shfl_xor_sync(0xffffffffu, mx1, 1));
            mx1 = fmaxf(mx1, __shfl_xor_sync(0xffffffffu, mx1, 2));

            const float mn0 = fmaxf(m0, mx0), mn1 = fmaxf(m1, mx1);
            const float a0 = __expf(m0 - mn0), a1 = __expf(m1 - mn1);
            l0 *= a0; l1 *= a1;
#pragma unroll
            for (int t = 0; t < 8; t++) {
                o[t][0] *= a0; o[t][1] *= a0; o[t][2] *= a1; o[t][3] *= a1;
            }
            float sl0 = 0.f, sl1 = 0.f;
#pragma unroll
            for (int t = 0; t < 8; t++) {
                s[t][0] = __expf(s[t][0] - mn0); s[t][1] = __expf(s[t][1] - mn0);
                s[t][2] = __expf(s[t][2] - mn1); s[t][3] = __expf(s[t][3] - mn1);
                sl0 += s[t][0] + s[t][1];
                sl1 += s[t][2] + s[t][3];
            }
            sl0 += __shfl_xor_sync(0xffffffffu, sl0, 1);
            sl0 += __shfl_xor_sync(0xffffffffu, sl0, 2);
            sl1 += __shfl_xor_sync(0xffffffffu, sl1, 1);
            sl1 += __shfl_xor_sync(0xffffffffu, sl1, 2);
            l0 += sl0; l1 += sl1;
            m0 = mn0; m1 = mn1;

            // ---- pack P single fp16 A-fragments ----
            uint32_t ph[8][2];
#pragma unroll
            for (int t = 0; t < 8; t++) {
                ph[t][0] = pk_h2(s[t][0], s[t][1]);
                ph[t][1] = pk_h2(s[t][2], s[t][3]);
            }

            // ---- O += P @ V (single pass) ----
#pragma unroll
            for (int kc = 0; kc < 4; kc++) {
                uint32_t ah[4] = {ph[2*kc][0], ph[2*kc][1], ph[2*kc+1][0], ph[2*kc+1][1]};
#pragma unroll
                for (int nt2 = 0; nt2 < 4; nt2++) {
                    const uint32_t voff =
                        (uint32_t)((kc * 16 + (lg & 1) * 8 + lr) * APAD + nt2 * 16 + (lg >> 1) * 8) * 2;
                    uint32_t f[4];
                    ldsm_x4_t(uVf + voff, f);
                    mma_f16(o[nt2 * 2],     ah, f);
                    mma_f16(o[nt2 * 2 + 1], ah, f + 2);
                }
            }
        }
        __syncthreads();
    }

    // ---- epilogue: normalize + single fp16 write ----
    const float inv0 = 1.f / l0, inv1 = 1.f / l1;
    const int row0 = qbaseG + quad;
    const size_t e0 = (((size_t)(b * S_ + row0)) * NH_ + h) * HD_ + qd * 2;
    const size_t e1 = (((size_t)(b * S_ + row0 + 8)) * NH_ + h) * HD_ + qd * 2;
#pragma unroll
    for (int t = 0; t < 8; t++) {
        *(uint32_t*)(aof + e0 + t * 8) = pk_h2(o[t][0] * inv0, o[t][1] * inv0);
        *(uint32_t*)(aof + e1 + t * 8) = pk_h2(o[t][2] * inv1, o[t][3] * inv1);
    }
}

// ---------------------------------------------------------------------------
extern "C" void kernel_launch(void* const* d_in, const int* in_sizes, int n_in,
                              void* d_out, int out_size)
{
    const float* x   = (const float*)d_in[0];
    const float* wq  = (const float*)d_in[1];
    const float* wk  = (const float*)d_in[2];
    const float* wv  = (const float*)d_in[3];
    const float* wo  = (const float*)d_in[4];
    const float* fcc = (const float*)d_in[5];
    const float* fcs = (const float*)d_in[6];
    (void)in_sizes; (void)n_in;

    __half *xh, *xl, *wqf, *wkf, *wvf, *wof;
    __half *qf, *kf, *vf, *aof;
    cudaGetSymbolAddress((void**)&xh,  g_xh);
    cudaGetSymbolAddress((void**)&xl,  g_xl);
    cudaGetSymbolAddress((void**)&wqf, g_wqf);
    cudaGetSymbolAddress((void**)&wkf, g_wkf);
    cudaGetSymbolAddress((void**)&wvf, g_wvf);
    cudaGetSymbolAddress((void**)&wof, g_wof);
    cudaGetSymbolAddress((void**)&qf,  g_qf);
    cudaGetSymbolAddress((void**)&kf,  g_kf);
    cudaGetSymbolAddress((void**)&vf,  g_vf);
    cudaGetSymbolAddress((void**)&aof, g_aof);

    cudaFuncSetAttribute(hgemm2,    cudaFuncAttributeMaxDynamicSharedMemorySize, HG_SMEM);
    cudaFuncSetAttribute(attn_mma2, cudaFuncAttributeMaxDynamicSharedMemorySize, AT_SMEM);

    const int M = M_;   // 8192

    // input prep
    split_h<<<(M * D_ / 4 + 255) / 256, 256>>>(x, xh, xl, M * D_ / 4);
    trans_conv<<<dim3(D_/32, D_/32), dim3(32, 8)>>>(wq, wqf, D_,   D_);
    trans_conv<<<dim3(D_/64, D_/32), dim3(32, 8)>>>(wk, wkf, D_/2, D_);
    trans_conv<<<dim3(D_/64, D_/32), dim3(32, 8)>>>(wv, wvf, D_/2, D_);
    trans_conv<<<dim3(D_/32, D_/32), dim3(32, 8)>>>(wo, wof, D_,   D_);

    // QKV projections with fused RoPE/convert epilogues
    hgemm2<<<dim3(NH_*HD_/128,  M/128), 256, HG_SMEM>>>(
        xh, xh, wqf, nullptr, qf, fcc, fcs, NH_*HD_,  D_, 2, 0.125f, 1);   // Q: 1-pass
    hgemm2<<<dim3(NKV_*HD_/128, M/128), 256, HG_SMEM>>>(
        xh, xl, wkf, nullptr, kf, fcc, fcs, NKV_*HD_, D_, 2, 1.0f, 2);     // K: 2-pass
    hgemm2<<<dim3(NKV_*HD_/128, M/128), 256, HG_SMEM>>>(
        xh, xh, wvf, nullptr, vf, fcc, fcs, NKV_*HD_, D_, 3, 1.0f, 1);     // V: 1-pass

    // Attention (all single fp16)
    attn_mma2<<<dim3(S_/128, NH_, B_), 256, AT_SMEM>>>(qf, kf, vf, aof);

    // Output projection (1-pass, fp32 out)
    hgemm2<<<dim3(D_/128, M/128), 256, HG_SMEM>>>(
        aof, aof, wof, (float*)d_out, nullptr, fcc, fcs, D_, D_, 0, 1.0f, 1);
    (void)out_size;
}